// round 2
// baseline (speedup 1.0000x reference)
#include <cuda_runtime.h>
#include <cuda_bf16.h>
#include <math.h>

// Problem constants
#define NN_MAX 100000
#define EE_MAX 1600000
#define DH 64

// ---------------- device scratch (no allocations allowed) ----------------
__device__ float g_tmp[NN_MAX * DH];   // (X @ W^T) * dinv  (message buffer)
__device__ float g_h[NN_MAX * DH];     // layer activations
__device__ float g_dinv[NN_MAX];
__device__ int   g_counts[NN_MAX];     // in-degree histogram
__device__ int   g_rowptr[NN_MAX + 1]; // CSR row pointers (by dst)
__device__ int   g_cursor[NN_MAX];     // fill cursors
__device__ int   g_esrc[EE_MAX];       // CSR column indices (src node ids)
__device__ int   g_blocksums[128];     // scan partials
__device__ float g_sums[DH];
__device__ float g_sumsq[DH];
__device__ float g_scale[DH];
__device__ float g_shift[DH];

// ---------------- CSR build ----------------
__global__ void zero_counts_kernel(int nn) {
    int i = blockIdx.x * blockDim.x + threadIdx.x;
    if (i < nn) g_counts[i] = 0;
}

__global__ void hist_kernel(const int* __restrict__ dst, int ee) {
    int e = blockIdx.x * blockDim.x + threadIdx.x;
    if (e < ee) atomicAdd(&g_counts[dst[e]], 1);
}

__global__ void dinv_kernel(int nn) {
    int i = blockIdx.x * blockDim.x + threadIdx.x;
    if (i < nn) g_dinv[i] = rsqrtf((float)(g_counts[i] + 1));  // +1 self loop
}

// block-wise inclusive scan of g_counts -> g_rowptr (inclusive-within-block)
__global__ void scan1_kernel(int nn) {
    __shared__ int s[1024];
    int t = threadIdx.x;
    int i = blockIdx.x * 1024 + t;
    int c = (i < nn) ? g_counts[i] : 0;
    s[t] = c;
    __syncthreads();
    for (int off = 1; off < 1024; off <<= 1) {
        int v = (t >= off) ? s[t - off] : 0;
        __syncthreads();
        s[t] += v;
        __syncthreads();
    }
    if (i < nn) g_rowptr[i] = s[t];
    if (t == 1023) g_blocksums[blockIdx.x] = s[1023];
}

__global__ void scan2_kernel(int nb) {
    __shared__ int s[128];
    int t = threadIdx.x;
    int v = (t < nb) ? g_blocksums[t] : 0;
    s[t] = v;
    __syncthreads();
    for (int off = 1; off < 128; off <<= 1) {
        int u = (t >= off) ? s[t - off] : 0;
        __syncthreads();
        s[t] += u;
        __syncthreads();
    }
    g_blocksums[t] = s[t] - v;  // exclusive
}

__global__ void scan3_kernel(int nn, int ee) {
    int i = blockIdx.x * 1024 + threadIdx.x;
    if (i < nn) {
        int excl = g_rowptr[i] - g_counts[i] + g_blocksums[blockIdx.x];
        g_rowptr[i] = excl;
        g_cursor[i] = excl;
    }
    if (i == 0) g_rowptr[nn] = ee;
}

__global__ void fill_kernel(const int* __restrict__ src, const int* __restrict__ dst, int ee) {
    int e = blockIdx.x * blockDim.x + threadIdx.x;
    if (e < ee) {
        int pos = atomicAdd(&g_cursor[dst[e]], 1);
        g_esrc[pos] = src[e];
    }
}

// ---------------- GEMM: g_tmp[n,:] = (X[n,:] @ W^T) * dinv[n] ----------------
// 64x64 output tile per block, 256 threads (16x16), 4x4 register tile, BK=64.
// USE_GH: read input from the device-global g_h (layers 2/3). NEVER pass
// __device__ globals as kernel args from host (host shadow address!).
template <int DIN, bool USE_GH>
__global__ void gemm_scale_kernel(const float* __restrict__ Xin,
                                  const float* __restrict__ W, int nn) {
    const float* __restrict__ X = USE_GH ? (const float*)g_h : Xin;
    float* __restrict__ out = g_tmp;

    __shared__ float Xs[64 * 68];  // transposed [k][n], stride 68
    __shared__ float Ws[64 * 68];  // transposed [k][j], stride 68
    int tid = threadIdx.x;
    int br = blockIdx.x * 64;
    int tx = tid & 15;   // col group (j0 = tx*4)
    int ty = tid >> 4;   // row group (n0 = ty*4)

    float acc[4][4];
#pragma unroll
    for (int i = 0; i < 4; i++)
#pragma unroll
        for (int j = 0; j < 4; j++) acc[i][j] = 0.0f;

    for (int kb = 0; kb < DIN; kb += 64) {
#pragma unroll
        for (int i = tid; i < 4096; i += 256) {
            int n = i >> 6, k = i & 63;
            int row = br + n;
            Xs[k * 68 + n] = (row < nn) ? X[row * DIN + kb + k] : 0.0f;
        }
#pragma unroll
        for (int i = tid; i < 4096; i += 256) {
            int j = i >> 6, k = i & 63;
            Ws[k * 68 + j] = W[j * DIN + kb + k];
        }
        __syncthreads();
#pragma unroll 8
        for (int k = 0; k < 64; k++) {
            float4 a = *(const float4*)&Xs[k * 68 + ty * 4];
            float4 b = *(const float4*)&Ws[k * 68 + tx * 4];
            float av[4] = {a.x, a.y, a.z, a.w};
            float bv[4] = {b.x, b.y, b.z, b.w};
#pragma unroll
            for (int i = 0; i < 4; i++)
#pragma unroll
                for (int j = 0; j < 4; j++) acc[i][j] += av[i] * bv[j];
        }
        __syncthreads();
    }

#pragma unroll
    for (int i = 0; i < 4; i++) {
        int row = br + ty * 4 + i;
        if (row < nn) {
            float dv = g_dinv[row];
            float4 r = make_float4(acc[i][0] * dv, acc[i][1] * dv, acc[i][2] * dv, acc[i][3] * dv);
            *(float4*)&out[row * DH + tx * 4] = r;
        }
    }
}

// ---------------- stats zero ----------------
__global__ void zero_stats_kernel() {
    int t = threadIdx.x;
    if (t < DH) { g_sums[t] = 0.0f; g_sumsq[t] = 0.0f; }
}

// ---------------- gather-aggregate + bias + BN stats ----------------
// warp per node; lane owns columns (2*lane, 2*lane+1) as float2.
__global__ void gather_kernel(const float* __restrict__ bias, int nn) {
    __shared__ float ss[DH];
    __shared__ float sq[DH];
    int tid = threadIdx.x;
    if (tid < DH) { ss[tid] = 0.0f; sq[tid] = 0.0f; }
    __syncthreads();

    const float2* __restrict__ tmp2 = (const float2*)g_tmp;
    float2* __restrict__ h2 = (float2*)g_h;

    int lane = tid & 31;
    int warp = blockIdx.x * (blockDim.x >> 5) + (tid >> 5);
    int nwarps = gridDim.x * (blockDim.x >> 5);

    float bx = bias[2 * lane];
    float by = bias[2 * lane + 1];
    float s0 = 0.f, s1 = 0.f, q0 = 0.f, q1 = 0.f;

    for (int n = warp; n < nn; n += nwarps) {
        int st = g_rowptr[n];
        int en = g_rowptr[n + 1];
        float2 self = tmp2[n * 32 + lane];
        float ax = self.x, ay = self.y;
        int e = st;
        for (; e + 4 <= en; e += 4) {
            int i0 = g_esrc[e], i1 = g_esrc[e + 1], i2 = g_esrc[e + 2], i3 = g_esrc[e + 3];
            float2 v0 = tmp2[i0 * 32 + lane];
            float2 v1 = tmp2[i1 * 32 + lane];
            float2 v2 = tmp2[i2 * 32 + lane];
            float2 v3 = tmp2[i3 * 32 + lane];
            ax += (v0.x + v1.x) + (v2.x + v3.x);
            ay += (v0.y + v1.y) + (v2.y + v3.y);
        }
        for (; e < en; e++) {
            int si = g_esrc[e];
            float2 v = tmp2[si * 32 + lane];
            ax += v.x; ay += v.y;
        }
        float dv = g_dinv[n];
        float rx = ax * dv + bx;
        float ry = ay * dv + by;
        h2[n * 32 + lane] = make_float2(rx, ry);
        s0 += rx; q0 += rx * rx;
        s1 += ry; q1 += ry * ry;
    }

    atomicAdd(&ss[2 * lane], s0);
    atomicAdd(&ss[2 * lane + 1], s1);
    atomicAdd(&sq[2 * lane], q0);
    atomicAdd(&sq[2 * lane + 1], q1);
    __syncthreads();
    if (tid < DH) {
        atomicAdd(&g_sums[tid], ss[tid]);
        atomicAdd(&g_sumsq[tid], sq[tid]);
    }
}

// ---------------- BN stats -> per-column scale/shift ----------------
__global__ void stats_final_kernel(const float* __restrict__ gamma,
                                   const float* __restrict__ beta, float invN) {
    int j = threadIdx.x;  // 64 threads
    float mean = g_sums[j] * invN;
    float var = g_sumsq[j] * invN - mean * mean;
    float sc = gamma[j] * rsqrtf(var + 1e-5f);
    g_scale[j] = sc;
    g_shift[j] = beta[j] - mean * sc;
}

// ---------------- BN apply + exact GELU (in place on g_h) ----------------
__global__ void bn_gelu_kernel(int total) {
    int i = blockIdx.x * blockDim.x + threadIdx.x;
    if (i >= total) return;
    int j = i & (DH - 1);
    float v = g_h[i] * g_scale[j] + g_shift[j];
    g_h[i] = 0.5f * v * (1.0f + erff(v * 0.70710678118654752440f));
}

// ---------------- final linear: out = h @ Wf^T + bf  (64 -> 10) ----------------
__global__ void final_kernel(const float* __restrict__ Wf, const float* __restrict__ bf,
                             float* __restrict__ out, int nn) {
    __shared__ float Hs[64][65];
    __shared__ float Ws[10][64];
    int tid = threadIdx.x;  // 128 threads
    int br = blockIdx.x * 64;

    for (int idx = tid; idx < 64 * 64; idx += 128) {
        int n = idx >> 6, k = idx & 63;
        int row = br + n;
        Hs[n][k] = (row < nn) ? g_h[row * DH + k] : 0.0f;
    }
    for (int idx = tid; idx < 640; idx += 128) {
        Ws[idx >> 6][idx & 63] = Wf[idx];
    }
    __syncthreads();

    int nl = tid & 63;
    int c0 = (tid >> 6) * 5;
    float acc[5];
#pragma unroll
    for (int c = 0; c < 5; c++) acc[c] = bf[c0 + c];
#pragma unroll 16
    for (int k = 0; k < 64; k++) {
        float hv = Hs[nl][k];
#pragma unroll
        for (int c = 0; c < 5; c++) acc[c] += hv * Ws[c0 + c][k];
    }
    int row = br + nl;
    if (row < nn) {
#pragma unroll
        for (int c = 0; c < 5; c++) out[row * 10 + c0 + c] = acc[c];
    }
}

// ---------------- host orchestration ----------------
extern "C" void kernel_launch(void* const* d_in, const int* in_sizes, int n_in,
                              void* d_out, int out_size) {
    const float* x  = (const float*)d_in[0];
    const int*   ei = (const int*)d_in[1];
    const float* W1 = (const float*)d_in[2];
    const float* b1 = (const float*)d_in[3];
    const float* g1 = (const float*)d_in[4];
    const float* be1 = (const float*)d_in[5];
    const float* W2 = (const float*)d_in[6];
    const float* b2 = (const float*)d_in[7];
    const float* g2 = (const float*)d_in[8];
    const float* be2 = (const float*)d_in[9];
    const float* W3 = (const float*)d_in[10];
    const float* b3 = (const float*)d_in[11];
    const float* g3 = (const float*)d_in[12];
    const float* be3 = (const float*)d_in[13];
    const float* Wf = (const float*)d_in[14];
    const float* bf = (const float*)d_in[15];
    float* out = (float*)d_out;

    int nn = in_sizes[0] / 128;      // 100000
    int ee = in_sizes[1] / 2;        // 1600000
    const int* src = ei;
    const int* dst = ei + ee;

    int nb_n = (nn + 255) / 256;
    int nb_e = (ee + 255) / 256;
    int nb_scan = (nn + 1023) / 1024;
    float invN = 1.0f / (float)nn;

    // ---- CSR build + dinv ----
    zero_counts_kernel<<<nb_n, 256>>>(nn);
    hist_kernel<<<nb_e, 256>>>(dst, ee);
    dinv_kernel<<<nb_n, 256>>>(nn);
    scan1_kernel<<<nb_scan, 1024>>>(nn);
    scan2_kernel<<<1, 128>>>(nb_scan);
    scan3_kernel<<<nb_scan, 1024>>>(nn, ee);
    fill_kernel<<<nb_e, 256>>>(src, dst, ee);

    int gemm_blocks = (nn + 63) / 64;
    int gather_blocks = 1184;           // 148 SMs * 8 blocks, grid-stride warps
    int bn_blocks = (nn * DH + 255) / 256;

    // ---- layer 1 (128 -> 64) ----
    zero_stats_kernel<<<1, 64>>>();
    gemm_scale_kernel<128, false><<<gemm_blocks, 256>>>(x, W1, nn);
    gather_kernel<<<gather_blocks, 256>>>(b1, nn);
    stats_final_kernel<<<1, 64>>>(g1, be1, invN);
    bn_gelu_kernel<<<bn_blocks, 256>>>(nn * DH);

    // ---- layer 2 (64 -> 64) ----
    zero_stats_kernel<<<1, 64>>>();
    gemm_scale_kernel<64, true><<<gemm_blocks, 256>>>(nullptr, W2, nn);
    gather_kernel<<<gather_blocks, 256>>>(b2, nn);
    stats_final_kernel<<<1, 64>>>(g2, be2, invN);
    bn_gelu_kernel<<<bn_blocks, 256>>>(nn * DH);

    // ---- layer 3 (64 -> 64) ----
    zero_stats_kernel<<<1, 64>>>();
    gemm_scale_kernel<64, true><<<gemm_blocks, 256>>>(nullptr, W3, nn);
    gather_kernel<<<gather_blocks, 256>>>(b3, nn);
    stats_final_kernel<<<1, 64>>>(g3, be3, invN);
    bn_gelu_kernel<<<bn_blocks, 256>>>(nn * DH);

    // ---- final classifier (64 -> 10) ----
    final_kernel<<<gemm_blocks, 128>>>(Wf, bf, out, nn);
}

// round 3
// speedup vs baseline: 1.1803x; 1.1803x over previous
#include <cuda_runtime.h>
#include <cuda_bf16.h>
#include <math.h>

#define NN_MAX 100000
#define EE_MAX 1600000
#define DH 64

// ---------------- device scratch ----------------
__device__ float g_tmp[NN_MAX * DH];   // (X @ W^T) * dinv  (message buffer)
__device__ float g_h[NN_MAX * DH];     // layer activations (pre-BN, post-bias)
__device__ float g_dinv[NN_MAX];
__device__ int   g_counts[NN_MAX];
__device__ int   g_rowptr[NN_MAX + 1];
__device__ int   g_cursor[NN_MAX];
__device__ int   g_esrc[EE_MAX];
__device__ int   g_blocksums[128];
__device__ float g_sums[DH];
__device__ float g_sumsq[DH];
__device__ float g_scale[DH];
__device__ float g_shift[DH];

__device__ __forceinline__ float gelu_f(float v) {
    return 0.5f * v * (1.0f + erff(v * 0.70710678118654752440f));
}

// ---------------- init: zero counts + stats ----------------
__global__ void init_kernel(int nn) {
    int i = blockIdx.x * blockDim.x + threadIdx.x;
    if (i < nn) g_counts[i] = 0;
    if (i < DH) { g_sums[i] = 0.0f; g_sumsq[i] = 0.0f; }
}

__global__ void hist_kernel(const int* __restrict__ dst, int ee) {
    int e = blockIdx.x * blockDim.x + threadIdx.x;
    if (e < ee) atomicAdd(&g_counts[dst[e]], 1);
}

// block-wise inclusive scan of g_counts
__global__ void scan1_kernel(int nn) {
    __shared__ int s[1024];
    int t = threadIdx.x;
    int i = blockIdx.x * 1024 + t;
    int c = (i < nn) ? g_counts[i] : 0;
    s[t] = c;
    __syncthreads();
    for (int off = 1; off < 1024; off <<= 1) {
        int v = (t >= off) ? s[t - off] : 0;
        __syncthreads();
        s[t] += v;
        __syncthreads();
    }
    if (i < nn) g_rowptr[i] = s[t];
    if (t == 1023) g_blocksums[blockIdx.x] = s[1023];
}

__global__ void scan2_kernel(int nb) {
    __shared__ int s[128];
    int t = threadIdx.x;
    int v = (t < nb) ? g_blocksums[t] : 0;
    s[t] = v;
    __syncthreads();
    for (int off = 1; off < 128; off <<= 1) {
        int u = (t >= off) ? s[t - off] : 0;
        __syncthreads();
        s[t] += u;
        __syncthreads();
    }
    g_blocksums[t] = s[t] - v;  // exclusive
}

// finalize rowptr/cursor + dinv (counts available here)
__global__ void scan3_kernel(int nn, int ee) {
    int i = blockIdx.x * 1024 + threadIdx.x;
    if (i < nn) {
        int c = g_counts[i];
        int excl = g_rowptr[i] - c + g_blocksums[blockIdx.x];
        g_rowptr[i] = excl;
        g_cursor[i] = excl;
        g_dinv[i] = rsqrtf((float)(c + 1));  // +1 self loop
    }
    if (i == 0) g_rowptr[nn] = ee;
}

__global__ void fill_kernel(const int* __restrict__ src, const int* __restrict__ dst, int ee) {
    int e = blockIdx.x * blockDim.x + threadIdx.x;
    if (e < ee) {
        int pos = atomicAdd(&g_cursor[dst[e]], 1);
        g_esrc[pos] = src[e];
    }
}

// ---------------- GEMM: g_tmp[n,:] = (act(X)[n,:] @ W^T) * dinv[n] ----------------
// 64x64 tile per block, 256 threads, 4x4 register tile, BK=64.
// APPLY_ACT: X element passes through BN(scale/shift)+GELU at load (DIN==64 path).
template <int DIN, bool USE_GH, bool APPLY_ACT>
__global__ void gemm_scale_kernel(const float* __restrict__ Xin,
                                  const float* __restrict__ W, int nn) {
    const float* __restrict__ X = USE_GH ? (const float*)g_h : Xin;
    float* __restrict__ out = g_tmp;

    __shared__ float Xs[64 * 68];  // [k][n]
    __shared__ float Ws[64 * 68];  // [k][j]
    __shared__ float s_sc[DH];
    __shared__ float s_sh[DH];
    int tid = threadIdx.x;
    int br = blockIdx.x * 64;
    int tx = tid & 15;
    int ty = tid >> 4;

    if (APPLY_ACT) {
        if (tid < DH) { s_sc[tid] = g_scale[tid]; s_sh[tid] = g_shift[tid]; }
        __syncthreads();
    }

    float acc[4][4];
#pragma unroll
    for (int i = 0; i < 4; i++)
#pragma unroll
        for (int j = 0; j < 4; j++) acc[i][j] = 0.0f;

    for (int kb = 0; kb < DIN; kb += 64) {
#pragma unroll
        for (int i = tid; i < 4096; i += 256) {
            int n = i >> 6, k = i & 63;
            int row = br + n;
            float v = (row < nn) ? X[row * DIN + kb + k] : 0.0f;
            if (APPLY_ACT) v = gelu_f(v * s_sc[k] + s_sh[k]);
            Xs[k * 68 + n] = v;
        }
#pragma unroll
        for (int i = tid; i < 4096; i += 256) {
            int j = i >> 6, k = i & 63;
            Ws[k * 68 + j] = W[j * DIN + kb + k];
        }
        __syncthreads();
#pragma unroll 8
        for (int k = 0; k < 64; k++) {
            float4 a = *(const float4*)&Xs[k * 68 + ty * 4];
            float4 b = *(const float4*)&Ws[k * 68 + tx * 4];
            float av[4] = {a.x, a.y, a.z, a.w};
            float bv[4] = {b.x, b.y, b.z, b.w};
#pragma unroll
            for (int i = 0; i < 4; i++)
#pragma unroll
                for (int j = 0; j < 4; j++) acc[i][j] += av[i] * bv[j];
        }
        __syncthreads();
    }

#pragma unroll
    for (int i = 0; i < 4; i++) {
        int row = br + ty * 4 + i;
        if (row < nn) {
            float dv = g_dinv[row];
            float4 r = make_float4(acc[i][0] * dv, acc[i][1] * dv, acc[i][2] * dv, acc[i][3] * dv);
            *(float4*)&out[row * DH + tx * 4] = r;
        }
    }
}

// ---------------- gather-aggregate + bias + BN stats ----------------
// warp per node; lane owns columns (2*lane, 2*lane+1) as float2. 8-wide unroll.
__global__ void gather_kernel(const float* __restrict__ bias, int nn) {
    __shared__ float ss[DH];
    __shared__ float sq[DH];
    int tid = threadIdx.x;
    if (tid < DH) { ss[tid] = 0.0f; sq[tid] = 0.0f; }
    __syncthreads();

    const float2* __restrict__ tmp2 = (const float2*)g_tmp;
    float2* __restrict__ h2 = (float2*)g_h;

    int lane = tid & 31;
    int warp = blockIdx.x * (blockDim.x >> 5) + (tid >> 5);
    int nwarps = gridDim.x * (blockDim.x >> 5);

    float bx = bias[2 * lane];
    float by = bias[2 * lane + 1];
    float s0 = 0.f, s1 = 0.f, q0 = 0.f, q1 = 0.f;

    for (int n = warp; n < nn; n += nwarps) {
        int st = g_rowptr[n];
        int en = g_rowptr[n + 1];
        float2 self = tmp2[n * 32 + lane];
        float ax = self.x, ay = self.y;
        int e = st;
        for (; e + 8 <= en; e += 8) {
            int idx[8];
#pragma unroll
            for (int u = 0; u < 8; u++) idx[u] = g_esrc[e + u];
            float2 v[8];
#pragma unroll
            for (int u = 0; u < 8; u++) v[u] = tmp2[idx[u] * 32 + lane];
            float px = ((v[0].x + v[1].x) + (v[2].x + v[3].x)) +
                       ((v[4].x + v[5].x) + (v[6].x + v[7].x));
            float py = ((v[0].y + v[1].y) + (v[2].y + v[3].y)) +
                       ((v[4].y + v[5].y) + (v[6].y + v[7].y));
            ax += px; ay += py;
        }
        for (; e < en; e++) {
            int si = g_esrc[e];
            float2 v = tmp2[si * 32 + lane];
            ax += v.x; ay += v.y;
        }
        float dv = g_dinv[n];
        float rx = ax * dv + bx;
        float ry = ay * dv + by;
        h2[n * 32 + lane] = make_float2(rx, ry);
        s0 += rx; q0 += rx * rx;
        s1 += ry; q1 += ry * ry;
    }

    atomicAdd(&ss[2 * lane], s0);
    atomicAdd(&ss[2 * lane + 1], s1);
    atomicAdd(&sq[2 * lane], q0);
    atomicAdd(&sq[2 * lane + 1], q1);
    __syncthreads();
    if (tid < DH) {
        atomicAdd(&g_sums[tid], ss[tid]);
        atomicAdd(&g_sumsq[tid], sq[tid]);
    }
}

// ---------------- BN stats -> scale/shift; re-zero stats for next layer ----------------
__global__ void stats_final_kernel(const float* __restrict__ gamma,
                                   const float* __restrict__ beta, float invN) {
    int j = threadIdx.x;  // 64 threads
    float mean = g_sums[j] * invN;
    float var = g_sumsq[j] * invN - mean * mean;
    float sc = gamma[j] * rsqrtf(var + 1e-5f);
    g_scale[j] = sc;
    g_shift[j] = beta[j] - mean * sc;
    g_sums[j] = 0.0f;
    g_sumsq[j] = 0.0f;
}

// ---------------- final: out = act(h) @ Wf^T + bf  (64 -> 10) ----------------
__global__ void final_kernel(const float* __restrict__ Wf, const float* __restrict__ bf,
                             float* __restrict__ out, int nn) {
    __shared__ float Hs[64][65];
    __shared__ float Ws[10][64];
    __shared__ float s_sc[DH];
    __shared__ float s_sh[DH];
    int tid = threadIdx.x;  // 128 threads
    int br = blockIdx.x * 64;

    if (tid < DH) { s_sc[tid] = g_scale[tid]; s_sh[tid] = g_shift[tid]; }
    __syncthreads();

    for (int idx = tid; idx < 64 * 64; idx += 128) {
        int n = idx >> 6, k = idx & 63;
        int row = br + n;
        float v = (row < nn) ? g_h[row * DH + k] : 0.0f;
        Hs[n][k] = gelu_f(v * s_sc[k] + s_sh[k]);
    }
    for (int idx = tid; idx < 640; idx += 128) {
        Ws[idx >> 6][idx & 63] = Wf[idx];
    }
    __syncthreads();

    int nl = tid & 63;
    int c0 = (tid >> 6) * 5;
    float acc[5];
#pragma unroll
    for (int c = 0; c < 5; c++) acc[c] = bf[c0 + c];
#pragma unroll 16
    for (int k = 0; k < 64; k++) {
        float hv = Hs[nl][k];
#pragma unroll
        for (int c = 0; c < 5; c++) acc[c] += hv * Ws[c0 + c][k];
    }
    int row = br + nl;
    if (row < nn) {
#pragma unroll
        for (int c = 0; c < 5; c++) out[row * 10 + c0 + c] = acc[c];
    }
}

// ---------------- host orchestration ----------------
extern "C" void kernel_launch(void* const* d_in, const int* in_sizes, int n_in,
                              void* d_out, int out_size) {
    const float* x  = (const float*)d_in[0];
    const int*   ei = (const int*)d_in[1];
    const float* W1 = (const float*)d_in[2];
    const float* b1 = (const float*)d_in[3];
    const float* g1 = (const float*)d_in[4];
    const float* be1 = (const float*)d_in[5];
    const float* W2 = (const float*)d_in[6];
    const float* b2 = (const float*)d_in[7];
    const float* g2 = (const float*)d_in[8];
    const float* be2 = (const float*)d_in[9];
    const float* W3 = (const float*)d_in[10];
    const float* b3 = (const float*)d_in[11];
    const float* g3 = (const float*)d_in[12];
    const float* be3 = (const float*)d_in[13];
    const float* Wf = (const float*)d_in[14];
    const float* bf = (const float*)d_in[15];
    float* out = (float*)d_out;

    int nn = in_sizes[0] / 128;      // 100000
    int ee = in_sizes[1] / 2;        // 1600000
    const int* src = ei;
    const int* dst = ei + ee;

    int nb_n = (nn + 255) / 256;
    int nb_e = (ee + 255) / 256;
    int nb_scan = (nn + 1023) / 1024;
    float invN = 1.0f / (float)nn;

    // ---- CSR build + dinv + stats init ----
    init_kernel<<<nb_n, 256>>>(nn);
    hist_kernel<<<nb_e, 256>>>(dst, ee);
    scan1_kernel<<<nb_scan, 1024>>>(nn);
    scan2_kernel<<<1, 128>>>(nb_scan);
    scan3_kernel<<<nb_scan, 1024>>>(nn, ee);
    fill_kernel<<<nb_e, 256>>>(src, dst, ee);

    int gemm_blocks = (nn + 63) / 64;
    int gather_blocks = 1184;

    // ---- layer 1 (128 -> 64): no input activation ----
    gemm_scale_kernel<128, false, false><<<gemm_blocks, 256>>>(x, W1, nn);
    gather_kernel<<<gather_blocks, 256>>>(b1, nn);
    stats_final_kernel<<<1, 64>>>(g1, be1, invN);

    // ---- layer 2 (64 -> 64): BN1+GELU fused into X load ----
    gemm_scale_kernel<64, true, true><<<gemm_blocks, 256>>>(nullptr, W2, nn);
    gather_kernel<<<gather_blocks, 256>>>(b2, nn);
    stats_final_kernel<<<1, 64>>>(g2, be2, invN);

    // ---- layer 3 (64 -> 64): BN2+GELU fused into X load ----
    gemm_scale_kernel<64, true, true><<<gemm_blocks, 256>>>(nullptr, W3, nn);
    gather_kernel<<<gather_blocks, 256>>>(b3, nn);
    stats_final_kernel<<<1, 64>>>(g3, be3, invN);

    // ---- final classifier (64 -> 10): BN3+GELU fused into H load ----
    final_kernel<<<gemm_blocks, 128>>>(Wf, bf, out, nn);
}